// round 9
// baseline (speedup 1.0000x reference)
#include <cuda_runtime.h>
#include <cuda_bf16.h>
#include <cstdint>

// Problem constants
#define Nn 100000
#define Ee 600000
#define D  128
#define NB_SCAN 391
#define MT 64                    // gemm tile rows (nodes)
#define NTILES 1563              // ceil(Nn/64)
#define THREADS_G 256

// smem byte offsets for k_gemm (row pitch 528 B = 264 bf16 / 132 f32)
#define PITCH 528
#define SB_WHI  0                // 128 rows * 528 = 67584
#define SB_WLO  67584
#define SB_AHI  135168           // 64 rows * 528 = 33792 (reused as C f32)
#define SB_ALO  168960
#define SB_BIAS 202752
#define SB_BNS  203264
#define SB_BNT  203776
#define SB_FCW  204288
#define SMEM_G  204544

typedef unsigned short ushort_t;
typedef unsigned int uint_t;

// ---------------- device scratch ------------------------------------------
__device__ int   g_deg[Nn];
__device__ int   g_off[Nn];
__device__ int   g_cur[Nn];
__device__ int   g_elist[Ee];
__device__ int   g_bsum[512];
__device__ __align__(16) float g_h[(size_t)Nn * D];
__device__ __align__(16) float g_mean[(size_t)Nn * D];
__device__ __align__(16) float g_bnsum[D];
__device__ __align__(16) float g_bnsq[D];
__device__ __align__(16) float g_bns[D];
__device__ __align__(16) float g_bnt[D];
__device__ float g_preds_fb[Nn];
__device__ __align__(16) float g_embed_fb[(size_t)Nn * D];

__device__ __forceinline__ void split_bf16(float v, ushort_t& h, ushort_t& l) {
    __nv_bfloat16 bh = __float2bfloat16(v);
    float r = v - __bfloat162float(bh);
    __nv_bfloat16 blo = __float2bfloat16(r);
    h = __bfloat16_as_ushort(bh);
    l = __bfloat16_as_ushort(blo);
}

// ---------------- CSR build ------------------------------------------------
__global__ void k_zero() {
    int i = blockIdx.x * blockDim.x + threadIdx.x;
    if (i < Nn) g_deg[i] = 0;
    if (i < D) { g_bnsum[i] = 0.f; g_bnsq[i] = 0.f; }
}
__global__ void k_degree(const int* __restrict__ dst) {
    int e = blockIdx.x * blockDim.x + threadIdx.x;
    if (e < Ee) atomicAdd(&g_deg[dst[e]], 1);
}
__global__ void k_scan1() {
    __shared__ int s[256];
    int i = blockIdx.x * 256 + threadIdx.x;
    int v = (i < Nn) ? g_deg[i] : 0;
    s[threadIdx.x] = v; __syncthreads();
    for (int d = 128; d > 0; d >>= 1) {
        if (threadIdx.x < d) s[threadIdx.x] += s[threadIdx.x + d];
        __syncthreads();
    }
    if (threadIdx.x == 0) g_bsum[blockIdx.x] = s[0];
}
__global__ void k_scan2() {
    __shared__ int s[512];
    int t = threadIdx.x;
    int v = (t < NB_SCAN) ? g_bsum[t] : 0;
    s[t] = v; __syncthreads();
    for (int d = 1; d < 512; d <<= 1) {
        int x = (t >= d) ? s[t - d] : 0;
        __syncthreads(); s[t] += x; __syncthreads();
    }
    if (t < NB_SCAN) g_bsum[t] = s[t] - v;
}
__global__ void k_scan3() {
    __shared__ int s[256];
    int t = threadIdx.x;
    int i = blockIdx.x * 256 + t;
    int v = (i < Nn) ? g_deg[i] : 0;
    s[t] = v; __syncthreads();
    for (int d = 1; d < 256; d <<= 1) {
        int x = (t >= d) ? s[t - d] : 0;
        __syncthreads(); s[t] += x; __syncthreads();
    }
    if (i < Nn) {
        int off = g_bsum[blockIdx.x] + s[t] - v;
        g_off[i] = off; g_cur[i] = off;
    }
}
__global__ void k_fill(const int* __restrict__ src, const int* __restrict__ dst) {
    int e = blockIdx.x * blockDim.x + threadIdx.x;
    if (e < Ee) {
        int p = atomicAdd(&g_cur[dst[e]], 1);
        g_elist[p] = src[e];
    }
}

// ---------------- mean aggregation (warp per node) -------------------------
__global__ __launch_bounds__(256)
void k_agg(const float* __restrict__ xin) {
    int w = (blockIdx.x * blockDim.x + threadIdx.x) >> 5;
    int lane = threadIdx.x & 31;
    if (w >= Nn) return;
    int off = g_off[w], dg = g_deg[w];
    const float4* xi4 = (const float4*)xin;
    float4 a0 = make_float4(0, 0, 0, 0), a1 = make_float4(0, 0, 0, 0);
    int e = 0;
    for (; e + 1 < dg; e += 2) {
        int s0 = __ldg(&g_elist[off + e]);
        int s1 = __ldg(&g_elist[off + e + 1]);
        float4 v0 = __ldg(&xi4[(size_t)s0 * 32 + lane]);
        float4 v1 = __ldg(&xi4[(size_t)s1 * 32 + lane]);
        a0.x += v0.x; a0.y += v0.y; a0.z += v0.z; a0.w += v0.w;
        a1.x += v1.x; a1.y += v1.y; a1.z += v1.z; a1.w += v1.w;
    }
    if (e < dg) {
        int s0 = __ldg(&g_elist[off + e]);
        float4 v0 = __ldg(&xi4[(size_t)s0 * 32 + lane]);
        a0.x += v0.x; a0.y += v0.y; a0.z += v0.z; a0.w += v0.w;
    }
    float inv = 1.f / (float)max(dg, 1);
    float4 m = make_float4((a0.x + a1.x) * inv, (a0.y + a1.y) * inv,
                           (a0.z + a1.z) * inv, (a0.w + a1.w) * inv);
    ((float4*)g_mean)[(size_t)w * 32 + lane] = m;
}

// ---------------- BN stats over g_h ----------------------------------------
__global__ __launch_bounds__(256)
void k_bnstats() {
    __shared__ float sh[256], shq[256];
    int col = threadIdx.x & 127;
    int rg  = threadIdx.x >> 7;
    size_t r0 = (size_t)blockIdx.x * 1024 + rg;
    float s = 0.f, q = 0.f;
    for (int i = 0; i < 512; i++) {
        size_t r = r0 + 2 * (size_t)i;
        if (r < Nn) {
            float v = g_h[r * D + col];
            s += v; q += v * v;
        }
    }
    sh[threadIdx.x] = s; shq[threadIdx.x] = q;
    __syncthreads();
    if (threadIdx.x < 128) {
        atomicAdd(&g_bnsum[col], sh[threadIdx.x] + sh[threadIdx.x + 128]);
        atomicAdd(&g_bnsq[col],  shq[threadIdx.x] + shq[threadIdx.x + 128]);
    }
}
__global__ void k_bnfin(const float* __restrict__ gamma,
                        const float* __restrict__ beta) {
    int j = threadIdx.x;
    if (j < D) {
        float mu  = g_bnsum[j] / (float)Nn;
        float var = g_bnsq[j] / (float)Nn - mu * mu;
        float s   = gamma[j] * rsqrtf(var + 1e-5f);
        g_bns[j] = s;
        g_bnt[j] = beta[j] - mu * s;
    }
}

// ---------------- mma.sync bf16 3-term-split GEMM + epilogue ---------------
// C[64 nodes][128] = A[64][256] @ W[256][128]; A row = [mean | x].
// A,W split hi/lo bf16; C = Ah*Wh + Ah*Wl + Al*Wh (fp32 accum).
// W stored transposed [n=128][k=256] with 528B pitch (conflict-free frags).
__global__ __launch_bounds__(THREADS_G, 1)
void k_gemm(const float* __restrict__ xin,
            const float* __restrict__ Wl, const float* __restrict__ Wr,
            const float* __restrict__ bl,
            float* __restrict__ hout, float* __restrict__ preds,
            const float* __restrict__ fcw, const float* __restrict__ fcb,
            int layer) {
    extern __shared__ char smg[];
    int tid = threadIdx.x;
    int warp = tid >> 5, lane = tid & 31;
    int g = lane >> 2, tg = lane & 3;
    int mw = warp & 1, nw = warp >> 1;

    float* sBias = (float*)(smg + SB_BIAS);
    float* sBns  = (float*)(smg + SB_BNS);
    float* sBnt  = (float*)(smg + SB_BNT);
    float* sFcw  = (float*)(smg + SB_FCW);

    // ---- stage W transposed + split (once per block) -----------------------
    for (int idx = tid; idx < 256 * 32; idx += THREADS_G) {
        int k = idx >> 5, q = idx & 31;
        float4 w = (k < 128) ? __ldg((const float4*)Wl + k * 32 + q)
                             : __ldg((const float4*)Wr + (k - 128) * 32 + q);
        float vv[4] = {w.x, w.y, w.z, w.w};
        #pragma unroll
        for (int j = 0; j < 4; j++) {
            int n = 4 * q + j;
            ushort_t h, l;
            split_bf16(vv[j], h, l);
            *(ushort_t*)(smg + SB_WHI + n * PITCH + k * 2) = h;
            *(ushort_t*)(smg + SB_WLO + n * PITCH + k * 2) = l;
        }
    }
    if (tid < 128) {
        sBias[tid] = bl[tid];
        if (layer == 2) { sBns[tid] = g_bns[tid]; sBnt[tid] = g_bnt[tid]; }
    }
    if (layer == 2 && tid < 64) sFcw[tid] = fcw[tid];
    __syncthreads();
    float fcb0 = (layer == 2) ? __ldg(fcb) : 0.f;

    int er = tid >> 2, part = tid & 3;     // epilogue/stage row & quarter

    for (int tile = blockIdx.x; tile < NTILES; tile += gridDim.x) {
        int base = tile * MT;
        // ---- stage A tile: 4 threads per row, 64 cols each -----------------
        {
            int node = base + er;
            bool valid = node < Nn;
            int dg = 1;
            if (layer == 2 && valid) dg = g_deg[node];
            int cb = part * 64;
            const float* srcp = (cb < 128)
                ? g_mean + (size_t)node * D + cb
                : xin + (size_t)node * D + (cb - 128);
            char* ah = smg + SB_AHI + er * PITCH + cb * 2;
            char* al = smg + SB_ALO + er * PITCH + cb * 2;
            bool zeroIt = !valid || (layer == 2 && cb < 128 && dg == 0);
            #pragma unroll
            for (int q = 0; q < 16; q++) {
                float4 f = make_float4(0, 0, 0, 0);
                if (!zeroIt) {
                    f = __ldg((const float4*)srcp + q);
                    if (layer == 2) {
                        int c = ((cb < 128) ? cb : cb - 128) + 4 * q;
                        f.x = f.x * sBns[c]     + sBnt[c];
                        f.y = f.y * sBns[c + 1] + sBnt[c + 1];
                        f.z = f.z * sBns[c + 2] + sBnt[c + 2];
                        f.w = f.w * sBns[c + 3] + sBnt[c + 3];
                    }
                }
                ushort_t h0, l0, h1, l1, h2, l2, h3, l3;
                split_bf16(f.x, h0, l0); split_bf16(f.y, h1, l1);
                split_bf16(f.z, h2, l2); split_bf16(f.w, h3, l3);
                *(uint_t*)(ah + 8 * q)     = (uint_t)h0 | ((uint_t)h1 << 16);
                *(uint_t*)(ah + 8 * q + 4) = (uint_t)h2 | ((uint_t)h3 << 16);
                *(uint_t*)(al + 8 * q)     = (uint_t)l0 | ((uint_t)l1 << 16);
                *(uint_t*)(al + 8 * q + 4) = (uint_t)l2 | ((uint_t)l3 << 16);
            }
        }
        __syncthreads();

        // ---- mma: warp tile 32(m) x 32(n), 2x4 m16n8 frags ----------------
        float acc[2][4][4];
        #pragma unroll
        for (int mi = 0; mi < 2; mi++)
            #pragma unroll
            for (int ni = 0; ni < 4; ni++)
                #pragma unroll
                for (int j = 0; j < 4; j++) acc[mi][ni][j] = 0.f;

        #pragma unroll 1
        for (int t = 0; t < 3; t++) {
            const char* aP = smg + ((t == 2) ? SB_ALO : SB_AHI);
            const char* bP = smg + ((t == 1) ? SB_WLO : SB_WHI);
            #pragma unroll 4
            for (int ks = 0; ks < 16; ks++) {
                int kb = ks * 32 + tg * 4;   // byte offset of k0+2*tg
                uint_t a0[2], a1[2], a2[2], a3[2];
                #pragma unroll
                for (int mi = 0; mi < 2; mi++) {
                    const char* ar = aP + (mw * 32 + mi * 16 + g) * PITCH + kb;
                    a0[mi] = *(const uint_t*)ar;
                    a1[mi] = *(const uint_t*)(ar + 8 * PITCH);
                    a2[mi] = *(const uint_t*)(ar + 16);
                    a3[mi] = *(const uint_t*)(ar + 8 * PITCH + 16);
                }
                #pragma unroll
                for (int ni = 0; ni < 4; ni++) {
                    const char* br = bP + (nw * 32 + ni * 8 + g) * PITCH + kb;
                    uint_t b0 = *(const uint_t*)br;
                    uint_t b1 = *(const uint_t*)(br + 16);
                    #pragma unroll
                    for (int mi = 0; mi < 2; mi++) {
                        asm volatile(
                            "mma.sync.aligned.m16n8k16.row.col.f32.bf16.bf16.f32 "
                            "{%0,%1,%2,%3}, {%4,%5,%6,%7}, {%8,%9}, {%0,%1,%2,%3};"
                            : "+f"(acc[mi][ni][0]), "+f"(acc[mi][ni][1]),
                              "+f"(acc[mi][ni][2]), "+f"(acc[mi][ni][3])
                            : "r"(a0[mi]), "r"(a1[mi]), "r"(a2[mi]), "r"(a3[mi]),
                              "r"(b0), "r"(b1));
                    }
                }
            }
        }
        __syncthreads();   // all sA reads complete before C overwrites it

        // ---- write C frags to smem (reuse A-hi region), 132 f32 pitch -----
        float* sC = (float*)(smg + SB_AHI);
        #pragma unroll
        for (int mi = 0; mi < 2; mi++) {
            #pragma unroll
            for (int ni = 0; ni < 4; ni++) {
                int row = mw * 32 + mi * 16 + g;
                int col = nw * 32 + ni * 8 + tg * 2;
                *(float2*)&sC[row * 132 + col] =
                    make_float2(acc[mi][ni][0], acc[mi][ni][1]);
                *(float2*)&sC[(row + 8) * 132 + col] =
                    make_float2(acc[mi][ni][2], acc[mi][ni][3]);
            }
        }
        __syncthreads();

        // ---- epilogue: 4 threads per row, bias + L2 norm + relu/preds -----
        {
            int node = base + er;
            float o[32];
            float ss = 0.f;
            #pragma unroll
            for (int i = 0; i < 32; i++) {
                int c = part * 32 + i;
                float v = sC[er * 132 + c] + sBias[c];
                o[i] = v; ss += v * v;
            }
            ss += __shfl_xor_sync(0xffffffffu, ss, 1);
            ss += __shfl_xor_sync(0xffffffffu, ss, 2);
            float inv = 1.f / fmaxf(sqrtf(ss), 1e-12f);
            if (node < Nn) {
                float4* hp = (float4*)(hout + (size_t)node * D + part * 32);
                if (layer == 1) {
                    #pragma unroll
                    for (int i = 0; i < 8; i++)
                        hp[i] = make_float4(fmaxf(o[4*i] * inv, 0.f),
                                            fmaxf(o[4*i+1] * inv, 0.f),
                                            fmaxf(o[4*i+2] * inv, 0.f),
                                            fmaxf(o[4*i+3] * inv, 0.f));
                } else {
                    #pragma unroll
                    for (int i = 0; i < 32; i++) o[i] *= inv;
                    #pragma unroll
                    for (int i = 0; i < 8; i++)
                        hp[i] = make_float4(o[4*i], o[4*i+1], o[4*i+2], o[4*i+3]);
                    float p = 0.f;
                    if (part < 2) {
                        #pragma unroll
                        for (int i = 0; i < 32; i++)
                            p += o[i] * sFcw[part * 32 + i];
                    }
                    p += __shfl_xor_sync(0xffffffffu, p, 1);
                    if (part == 0) preds[node] = p + fcb0;
                }
            }
        }
        __syncthreads();
    }
}

// ---------------- launch ----------------------------------------------------
extern "C" void kernel_launch(void* const* d_in, const int* in_sizes, int n_in,
                              void* d_out, int out_size) {
    const float* x     = (const float*)d_in[0];
    const int*   ei    = (const int*)d_in[1];
    const int*   src   = ei;
    const int*   dst   = ei + Ee;
    const float* W1l   = (const float*)d_in[2];
    const float* b1l   = (const float*)d_in[3];
    const float* W1r   = (const float*)d_in[4];
    const float* gamma = (const float*)d_in[5];
    const float* beta  = (const float*)d_in[6];
    const float* W2l   = (const float*)d_in[7];
    const float* b2l   = (const float*)d_in[8];
    const float* W2r   = (const float*)d_in[9];
    const float* fcw   = (const float*)d_in[10];
    const float* fcb   = (const float*)d_in[11];

    float* ph = nullptr;
    cudaGetSymbolAddress((void**)&ph, g_h);

    float* out = (float*)d_out;
    float* preds;
    float* embed;
    if (out_size == Nn + Nn * D) {
        preds = out;
        embed = out + Nn;
    } else if (out_size == Nn * D) {
        embed = out;
        cudaGetSymbolAddress((void**)&preds, g_preds_fb);
    } else {
        preds = out;
        cudaGetSymbolAddress((void**)&embed, g_embed_fb);
    }

    int sms = 148;
    cudaDeviceGetAttribute(&sms, cudaDevAttrMultiProcessorCount, 0);
    cudaFuncSetAttribute(k_gemm, cudaFuncAttributeMaxDynamicSharedMemorySize, SMEM_G);

    k_zero<<<(Nn + 255) / 256, 256>>>();
    k_degree<<<(Ee + 255) / 256, 256>>>(dst);
    k_scan1<<<NB_SCAN, 256>>>();
    k_scan2<<<1, 512>>>();
    k_scan3<<<NB_SCAN, 256>>>();
    k_fill<<<(Ee + 255) / 256, 256>>>(src, dst);

    k_agg<<<(Nn * 32 + 255) / 256, 256>>>(x);
    k_gemm<<<sms, THREADS_G, SMEM_G>>>(x, W1l, W1r, b1l, ph, nullptr,
                                       nullptr, nullptr, 1);
    k_bnstats<<<98, 256>>>();
    k_bnfin<<<1, 128>>>(gamma, beta);
    k_agg<<<(Nn * 32 + 255) / 256, 256>>>(ph);
    k_gemm<<<sms, THREADS_G, SMEM_G>>>(ph, W2l, W2r, b2l, embed, preds,
                                       fcw, fcb, 2);
}